// round 15
// baseline (speedup 1.0000x reference)
#include <cuda_runtime.h>
#include <cuda_bf16.h>
#include <cstdint>

#define Nn 384
#define Dm 256
#define MARGIN 0.2f
#define AB 8                 // anchors per block
#define NBLKS (Nn / AB)      // 48
#define NTHR 384
#define NWARP 12

typedef unsigned u32;

__device__ __nv_bfloat16 g_ehi[Nn * Dm];
__device__ __nv_bfloat16 g_elo[Nn * Dm];
__device__ float g_psum[NBLKS];
__device__ int   g_pcnt[NBLKS];
__device__ u32   g_ready;   // zero-init; reset by last block each run
__device__ u32   g_flag;    // zero-init; reset by last block each run

static __device__ __forceinline__ u32 packbf(float a, float b) {
    __nv_bfloat162 h = __floats2bfloat162_rn(a, b);
    u32 r; memcpy(&r, &h, 4); return r;
}

static __device__ __forceinline__ void mma_bf16(
    float& c0, float& c1, float& c2, float& c3,
    u32 a0, u32 a1, u32 a2, u32 a3, u32 b0, u32 b1) {
    asm volatile(
        "mma.sync.aligned.m16n8k16.row.col.f32.bf16.bf16.f32 "
        "{%0,%1,%2,%3},{%4,%5,%6,%7},{%8,%9},{%0,%1,%2,%3};"
        : "+f"(c0), "+f"(c1), "+f"(c2), "+f"(c3)
        : "r"(a0), "r"(a1), "r"(a2), "r"(a3), "r"(b0), "r"(b1));
}

__global__ void __launch_bounds__(NTHR, 1)
k_fused(const float* __restrict__ e, const int* __restrict__ lab,
        float* __restrict__ out) {
    __shared__ float Drow[AB][Nn];     // distances anchor -> all j
    __shared__ int   slab[Nn];
    __shared__ float pd[Nn];           // compacted positive distances
    __shared__ int   wcnt[NWARP];
    __shared__ float rsum[NWARP];
    __shared__ int   rcnt[NWARP];
    __shared__ int   s_last;

    const int t = threadIdx.x, w = t >> 5, lane = t & 31;
    const int bid = blockIdx.x;
    const int a0g = bid * AB;
    const int gr  = lane >> 2;     // groupID (0..7)
    const int tig = lane & 3;      // thread-in-group (0..3)

    if (t < Nn) slab[t] = lab[t];

    // ---- Phase A: normalize rows a0g..a0g+7, store bf16 hi/lo splits ----
    if (w < AB) {
        const int row = a0g + w;
        const float4* src = (const float4*)(e + row * Dm);
        float4 x0 = src[lane], x1 = src[lane + 32];
        float s = x0.x * x0.x;
        s = fmaf(x0.y, x0.y, s); s = fmaf(x0.z, x0.z, s); s = fmaf(x0.w, x0.w, s);
        s = fmaf(x1.x, x1.x, s); s = fmaf(x1.y, x1.y, s);
        s = fmaf(x1.z, x1.z, s); s = fmaf(x1.w, x1.w, s);
        #pragma unroll
        for (int o = 16; o > 0; o >>= 1) s += __shfl_xor_sync(0xffffffffu, s, o);
        const float inv = rsqrtf(fmaxf(s, 1e-24f));
        float nv[8] = { x0.x * inv, x0.y * inv, x0.z * inv, x0.w * inv,
                        x1.x * inv, x1.y * inv, x1.z * inv, x1.w * inv };
        float hi[8], lo[8];
        #pragma unroll
        for (int i = 0; i < 8; i++) {
            __nv_bfloat16 h = __float2bfloat16(nv[i]);
            hi[i] = __bfloat162float(h);
            lo[i] = nv[i] - hi[i];
        }
        u32* dh = (u32*)(g_ehi + row * Dm);
        u32* dl = (u32*)(g_elo + row * Dm);
        dh[lane * 2 + 0]      = packbf(hi[0], hi[1]);
        dh[lane * 2 + 1]      = packbf(hi[2], hi[3]);
        dh[64 + lane * 2 + 0] = packbf(hi[4], hi[5]);
        dh[64 + lane * 2 + 1] = packbf(hi[6], hi[7]);
        dl[lane * 2 + 0]      = packbf(lo[0], lo[1]);
        dl[lane * 2 + 1]      = packbf(lo[2], lo[3]);
        dl[64 + lane * 2 + 0] = packbf(lo[4], lo[5]);
        dl[64 + lane * 2 + 1] = packbf(lo[6], lo[7]);
    }

    // ---- Grid barrier: all 48 co-resident blocks finished phase A ----
    __syncthreads();
    if (t == 0) {
        __threadfence();
        atomicAdd(&g_ready, 1u);
        while (*(volatile u32*)&g_ready < (u32)NBLKS) { }
        __threadfence();
    }
    __syncthreads();

    // ---- Phase B: mma.sync Gram tiles. Warp w covers j-tiles {2w, 2w+1} ----
    // m16n8k16: A = 16 j-rows x 16 k (row-major), B = 16 k x 8 anchors (col-major)
    #pragma unroll
    for (int jt = 2 * w; jt < 2 * w + 2; jt++) {
        const int j0 = jt * 16;
        float hh0 = 0.f, hh1 = 0.f, hh2 = 0.f, hh3 = 0.f;
        float hl0 = 0.f, hl1 = 0.f, hl2 = 0.f, hl3 = 0.f;
        float lh0 = 0.f, lh1 = 0.f, lh2 = 0.f, lh3 = 0.f;
        #pragma unroll 4
        for (int kt = 0; kt < 16; kt++) {
            const int k0 = kt * 16;
            // A fragments: a0/a2 from row j0+gr, a1/a3 from row j0+gr+8
            const u32* Ah0 = (const u32*)(g_ehi + (j0 + gr) * Dm + k0);
            const u32* Ah1 = (const u32*)(g_ehi + (j0 + gr + 8) * Dm + k0);
            const u32* Al0 = (const u32*)(g_elo + (j0 + gr) * Dm + k0);
            const u32* Al1 = (const u32*)(g_elo + (j0 + gr + 8) * Dm + k0);
            u32 ah0 = Ah0[tig], ah2 = Ah0[tig + 4];
            u32 ah1 = Ah1[tig], ah3 = Ah1[tig + 4];
            u32 al0 = Al0[tig], al2 = Al0[tig + 4];
            u32 al1 = Al1[tig], al3 = Al1[tig + 4];
            // B fragments: anchor row a0g+gr (col n = gr), k pairs at tig*2 / tig*2+8
            const u32* Bh = (const u32*)(g_ehi + (a0g + gr) * Dm + k0);
            const u32* Bl = (const u32*)(g_elo + (a0g + gr) * Dm + k0);
            u32 bh0 = Bh[tig], bh1 = Bh[tig + 4];
            u32 bl0 = Bl[tig], bl1 = Bl[tig + 4];
            mma_bf16(hh0, hh1, hh2, hh3, ah0, ah1, ah2, ah3, bh0, bh1);
            mma_bf16(hl0, hl1, hl2, hl3, ah0, ah1, ah2, ah3, bl0, bl1);
            mma_bf16(lh0, lh1, lh2, lh3, al0, al1, al2, al3, bh0, bh1);
        }
        const float g0 = hh0 + hl0 + lh0;
        const float g1 = hh1 + hl1 + lh1;
        const float g2 = hh2 + hl2 + lh2;
        const float g3 = hh3 + hl3 + lh3;
        // C layout: c0/c1 row j0+gr cols 2*tig/2*tig+1; c2/c3 row j0+gr+8
        float d2;
        d2 = fmaxf(2.0f - 2.0f * g0, 0.0f);
        Drow[2 * tig + 0][j0 + gr]     = (d2 > 0.0f) ? sqrtf(d2) : 0.0f;
        d2 = fmaxf(2.0f - 2.0f * g1, 0.0f);
        Drow[2 * tig + 1][j0 + gr]     = (d2 > 0.0f) ? sqrtf(d2) : 0.0f;
        d2 = fmaxf(2.0f - 2.0f * g2, 0.0f);
        Drow[2 * tig + 0][j0 + gr + 8] = (d2 > 0.0f) ? sqrtf(d2) : 0.0f;
        d2 = fmaxf(2.0f - 2.0f * g3, 0.0f);
        Drow[2 * tig + 1][j0 + gr + 8] = (d2 > 0.0f) ? sqrtf(d2) : 0.0f;
    }
    __syncthreads();

    // ---- Phase C: per anchor, ballot-compaction of positives + negative scan ----
    const int myl = slab[t];
    float lsum = 0.0f;
    int   lcnt = 0;
    #pragma unroll 1
    for (int aa = 0; aa < AB; aa++) {
        const int a  = a0g + aa;
        const int la = slab[a];
        const float dn = Drow[aa][t];
        const bool isp = (myl == la) && (t != a);
        const unsigned m = __ballot_sync(0xffffffffu, isp);
        if (lane == 0) wcnt[w] = __popc(m);
        __syncthreads();
        int off = 0, npos = 0;
        #pragma unroll
        for (int i = 0; i < NWARP; i++) {
            const int c = wcnt[i];
            if (i < w) off += c;
            npos += c;
        }
        if (isp) pd[off + __popc(m & ((1u << lane) - 1u))] = dn;
        __syncthreads();

        if (myl != la) {
            for (int i = 0; i < npos; i++) {
                const float tm = dn - pd[i];
                // semihard & loss>0  <=>  0 < tm < MARGIN (tm==MARGIN adds 0)
                if (tm > 0.0f && tm < MARGIN) { lsum += (MARGIN - tm); lcnt++; }
            }
        }
        __syncthreads();
    }

    // ---- Block reduction (fixed order, deterministic) ----
    #pragma unroll
    for (int o = 16; o > 0; o >>= 1) {
        lsum += __shfl_xor_sync(0xffffffffu, lsum, o);
        lcnt += __shfl_xor_sync(0xffffffffu, lcnt, o);
    }
    if (lane == 0) { rsum[w] = lsum; rcnt[w] = lcnt; }
    __syncthreads();
    if (t == 0) {
        float s = 0.0f; int c = 0;
        #pragma unroll
        for (int i = 0; i < NWARP; i++) { s += rsum[i]; c += rcnt[i]; }
        g_psum[bid] = s;
        g_pcnt[bid] = c;
        __threadfence();
        const u32 old = atomicAdd(&g_flag, 1u);
        s_last = (old == NBLKS - 1) ? 1 : 0;
    }
    __syncthreads();

    // ---- Last block folds the 48 partials (deterministic order) ----
    if (s_last) {
        float s2 = (t < NBLKS) ? g_psum[t] : 0.0f;
        int   c2 = (t < NBLKS) ? g_pcnt[t] : 0;
        #pragma unroll
        for (int o = 16; o > 0; o >>= 1) {
            s2 += __shfl_xor_sync(0xffffffffu, s2, o);
            c2 += __shfl_xor_sync(0xffffffffu, c2, o);
        }
        if (lane == 0 && w < 2) { rsum[w] = s2; rcnt[w] = c2; }
        __syncthreads();
        if (t == 0) {
            const float ts = rsum[0] + rsum[1];
            const int   tc = rcnt[0] + rcnt[1];
            out[0] = (tc > 0) ? (ts / (float)tc) : 0.0f;
            g_flag  = 0;   // reset for next graph replay
            g_ready = 0;
        }
    }
}

extern "C" void kernel_launch(void* const* d_in, const int* in_sizes, int n_in,
                              void* d_out, int out_size) {
    const float* e   = (const float*)d_in[0];
    const int*   lab = (const int*)d_in[1];
    k_fused<<<NBLKS, NTHR>>>(e, lab, (float*)d_out);
}

// round 16
// speedup vs baseline: 1.6199x; 1.6199x over previous
#include <cuda_runtime.h>
#include <cuda_bf16.h>
#include <cstdint>

#define Nn 384
#define Dm 256
#define MARGIN 0.2f
#define AB 8                 // anchors per block
#define NBLKS 48
#define NTHR 384
#define NWARP 12
#define CH_ROWS 192          // rows per chunk
#define ROW_B 512            // bytes per bf16 row
#define HI_BYTES (CH_ROWS * ROW_B)          // 98304
#define OFF_LO   HI_BYTES
#define OFF_DROW (2 * HI_BYTES)             // 196608
#define OFF_SLAB (OFF_DROW + AB * Nn * 4)   // 208896
#define OFF_PD   (OFF_SLAB + Nn * 4)        // 210432
#define OFF_WCNT (OFF_PD + Nn * 4)          // 211968
#define OFF_RSUM (OFF_WCNT + NWARP * 4)
#define OFF_RCNT (OFF_RSUM + NWARP * 4)
#define OFF_SLAST (OFF_RCNT + NWARP * 4)
#define SMEM_TOTAL (OFF_SLAST + 16)         // ~212 KB

typedef unsigned u32;

__device__ __nv_bfloat16 g_ehi[Nn * Dm];
__device__ __nv_bfloat16 g_elo[Nn * Dm];
__device__ float g_psum[NBLKS];
__device__ int   g_pcnt[NBLKS];
__device__ u32   g_ready;   // zero-init; reset by last block each run
__device__ u32   g_flag;    // zero-init; reset by last block each run

static __device__ __forceinline__ u32 packbf(float a, float b) {
    __nv_bfloat162 h = __floats2bfloat162_rn(a, b);
    u32 r; memcpy(&r, &h, 4); return r;
}
static __device__ __forceinline__ u32 smem_u32(const void* p) {
    u32 a;
    asm("{ .reg .u64 t; cvta.to.shared.u64 t, %1; cvt.u32.u64 %0, t; }"
        : "=r"(a) : "l"(p));
    return a;
}
static __device__ __forceinline__ void cp16(u32 dst, const void* src) {
    asm volatile("cp.async.cg.shared.global [%0], [%1], 16;"
                 :: "r"(dst), "l"(src));
}
static __device__ __forceinline__ void ldm4(u32& r0, u32& r1, u32& r2, u32& r3, u32 addr) {
    asm volatile("ldmatrix.sync.aligned.m8n8.x4.shared.b16 {%0,%1,%2,%3}, [%4];"
                 : "=r"(r0), "=r"(r1), "=r"(r2), "=r"(r3) : "r"(addr));
}
static __device__ __forceinline__ void mma_bf16(
    float& c0, float& c1, float& c2, float& c3,
    u32 a0, u32 a1, u32 a2, u32 a3, u32 b0, u32 b1) {
    asm volatile(
        "mma.sync.aligned.m16n8k16.row.col.f32.bf16.bf16.f32 "
        "{%0,%1,%2,%3},{%4,%5,%6,%7},{%8,%9},{%0,%1,%2,%3};"
        : "+f"(c0), "+f"(c1), "+f"(c2), "+f"(c3)
        : "r"(a0), "r"(a1), "r"(a2), "r"(a3), "r"(b0), "r"(b1));
}

__global__ void __launch_bounds__(NTHR, 1)
k_fused(const float* __restrict__ e, const int* __restrict__ lab,
        float* __restrict__ out) {
    extern __shared__ __align__(1024) char sm[];
    float (*Drow)[Nn] = (float(*)[Nn])(sm + OFF_DROW);
    int*   slab = (int*)(sm + OFF_SLAB);
    float* pd   = (float*)(sm + OFF_PD);
    int*   wcnt = (int*)(sm + OFF_WCNT);
    float* rsum = (float*)(sm + OFF_RSUM);
    int*   rcnt = (int*)(sm + OFF_RCNT);
    int*   s_last = (int*)(sm + OFF_SLAST);
    const u32 sbase = smem_u32(sm);

    const int t = threadIdx.x, w = t >> 5, lane = t & 31;
    const int bid = blockIdx.x;
    const int a0g = bid * AB;
    const int gr  = lane >> 2;     // mma groupID (0..7)
    const int tig = lane & 3;      // mma thread-in-group (0..3)

    if (t < Nn) slab[t] = lab[t];

    // ---- Phase A: normalize rows a0g..a0g+7, store bf16 hi/lo splits ----
    if (w < AB) {
        const int row = a0g + w;
        const float4* src = (const float4*)(e + row * Dm);
        float4 x0 = src[lane], x1 = src[lane + 32];
        float s = x0.x * x0.x;
        s = fmaf(x0.y, x0.y, s); s = fmaf(x0.z, x0.z, s); s = fmaf(x0.w, x0.w, s);
        s = fmaf(x1.x, x1.x, s); s = fmaf(x1.y, x1.y, s);
        s = fmaf(x1.z, x1.z, s); s = fmaf(x1.w, x1.w, s);
        #pragma unroll
        for (int o = 16; o > 0; o >>= 1) s += __shfl_xor_sync(0xffffffffu, s, o);
        const float inv = rsqrtf(fmaxf(s, 1e-24f));
        float nv[8] = { x0.x * inv, x0.y * inv, x0.z * inv, x0.w * inv,
                        x1.x * inv, x1.y * inv, x1.z * inv, x1.w * inv };
        float hi[8], lo[8];
        #pragma unroll
        for (int i = 0; i < 8; i++) {
            __nv_bfloat16 h = __float2bfloat16(nv[i]);
            hi[i] = __bfloat162float(h);
            lo[i] = nv[i] - hi[i];
        }
        u32* dh = (u32*)(g_ehi + row * Dm);
        u32* dl = (u32*)(g_elo + row * Dm);
        dh[lane * 2 + 0]      = packbf(hi[0], hi[1]);
        dh[lane * 2 + 1]      = packbf(hi[2], hi[3]);
        dh[64 + lane * 2 + 0] = packbf(hi[4], hi[5]);
        dh[64 + lane * 2 + 1] = packbf(hi[6], hi[7]);
        dl[lane * 2 + 0]      = packbf(lo[0], lo[1]);
        dl[lane * 2 + 1]      = packbf(lo[2], lo[3]);
        dl[64 + lane * 2 + 0] = packbf(lo[4], lo[5]);
        dl[64 + lane * 2 + 1] = packbf(lo[6], lo[7]);
    }
    __syncthreads();   // own block's hi/lo rows visible block-wide

    // ---- Hoist B fragments (this block's 8 anchors) into registers ----
    u32 bh[32], bl[32];
    {
        const u32* Bh32 = (const u32*)(g_ehi + (a0g + gr) * Dm);
        const u32* Bl32 = (const u32*)(g_elo + (a0g + gr) * Dm);
        #pragma unroll
        for (int kt = 0; kt < 16; kt++) {
            bh[2 * kt + 0] = Bh32[kt * 8 + tig];
            bh[2 * kt + 1] = Bh32[kt * 8 + tig + 4];
            bl[2 * kt + 0] = Bl32[kt * 8 + tig];
            bl[2 * kt + 1] = Bl32[kt * 8 + tig + 4];
        }
    }

    // ---- Grid barrier: all 48 co-resident blocks finished phase A ----
    if (t == 0) {
        __threadfence();
        atomicAdd(&g_ready, 1u);
        while (*(volatile u32*)&g_ready < (u32)NBLKS) { }
        __threadfence();
    }
    __syncthreads();

    // ---- Phase B: 2 chunks of 192 rows staged in smem; ldmatrix + mma ----
    // ldmatrix addressing: lane -> matrix m (0..3), row-in-matrix rr
    const int m_ = lane >> 3, rr = lane & 7;
    const u32 lm_row = (u32)(w * 16 + ((m_ & 1) << 3) + rr);   // 0..191
    const u32 lm_base = sbase + lm_row * ROW_B;
    const u32 lm_xm = (lm_row & 7) << 4;
    const u32 cb2 = (u32)(m_ >> 1) << 4;                        // 0 or 16 bytes

    #pragma unroll 1
    for (int c = 0; c < 2; c++) {
        // stage 192 rows hi+lo, coalesced 16B cp.async, swizzled rows
        #pragma unroll
        for (int i = 0; i < 16; i++) {
            const int u = t + i * NTHR;
            const int r = u >> 5, q = u & 31;
            const u32 off = (u32)(r * ROW_B) + (((u32)(q * 16)) ^ ((u32)(r & 7) << 4));
            cp16(sbase + off, (const char*)g_ehi + (c * CH_ROWS + r) * ROW_B + q * 16);
            cp16(sbase + OFF_LO + off, (const char*)g_elo + (c * CH_ROWS + r) * ROW_B + q * 16);
        }
        asm volatile("cp.async.commit_group;");
        asm volatile("cp.async.wait_group 0;");
        __syncthreads();

        // compute: warp w owns j-tile rows [w*16, w*16+16) within chunk
        float hh0 = 0.f, hh1 = 0.f, hh2 = 0.f, hh3 = 0.f;
        float hl0 = 0.f, hl1 = 0.f, hl2 = 0.f, hl3 = 0.f;
        float lh0 = 0.f, lh1 = 0.f, lh2 = 0.f, lh3 = 0.f;
        #pragma unroll
        for (int kt = 0; kt < 16; kt++) {
            const u32 col = ((u32)(kt * 32) + cb2) ^ lm_xm;
            u32 ah0, ah1, ah2, ah3, al0, al1, al2, al3;
            ldm4(ah0, ah1, ah2, ah3, lm_base + col);
            ldm4(al0, al1, al2, al3, lm_base + OFF_LO + col);
            mma_bf16(hh0, hh1, hh2, hh3, ah0, ah1, ah2, ah3, bh[2*kt], bh[2*kt+1]);
            mma_bf16(hl0, hl1, hl2, hl3, ah0, ah1, ah2, ah3, bl[2*kt], bl[2*kt+1]);
            mma_bf16(lh0, lh1, lh2, lh3, al0, al1, al2, al3, bh[2*kt], bh[2*kt+1]);
        }
        const int j0 = c * CH_ROWS + w * 16;
        const float g0 = hh0 + hl0 + lh0;
        const float g1 = hh1 + hl1 + lh1;
        const float g2 = hh2 + hl2 + lh2;
        const float g3 = hh3 + hl3 + lh3;
        float d2;
        d2 = fmaxf(2.0f - 2.0f * g0, 0.0f);
        Drow[2 * tig + 0][j0 + gr]     = (d2 > 0.0f) ? sqrtf(d2) : 0.0f;
        d2 = fmaxf(2.0f - 2.0f * g1, 0.0f);
        Drow[2 * tig + 1][j0 + gr]     = (d2 > 0.0f) ? sqrtf(d2) : 0.0f;
        d2 = fmaxf(2.0f - 2.0f * g2, 0.0f);
        Drow[2 * tig + 0][j0 + gr + 8] = (d2 > 0.0f) ? sqrtf(d2) : 0.0f;
        d2 = fmaxf(2.0f - 2.0f * g3, 0.0f);
        Drow[2 * tig + 1][j0 + gr + 8] = (d2 > 0.0f) ? sqrtf(d2) : 0.0f;
        __syncthreads();    // chunk buffer free before next stage
    }

    // ---- Phase C: per anchor, ballot-compaction of positives + negative scan ----
    const int myl = slab[t];
    float lsum = 0.0f;
    int   lcnt = 0;
    #pragma unroll 1
    for (int aa = 0; aa < AB; aa++) {
        const int a  = a0g + aa;
        const int la = slab[a];
        const float dn = Drow[aa][t];
        const bool isp = (myl == la) && (t != a);
        const unsigned m = __ballot_sync(0xffffffffu, isp);
        if (lane == 0) wcnt[w] = __popc(m);
        __syncthreads();
        int off = 0, npos = 0;
        #pragma unroll
        for (int i = 0; i < NWARP; i++) {
            const int cc = wcnt[i];
            if (i < w) off += cc;
            npos += cc;
        }
        if (isp) pd[off + __popc(m & ((1u << lane) - 1u))] = dn;
        __syncthreads();

        if (myl != la) {
            for (int i = 0; i < npos; i++) {
                const float tm = dn - pd[i];
                // semihard & loss>0  <=>  0 < tm < MARGIN (tm==MARGIN adds 0)
                if (tm > 0.0f && tm < MARGIN) { lsum += (MARGIN - tm); lcnt++; }
            }
        }
        __syncthreads();
    }

    // ---- Block reduction (fixed order, deterministic) ----
    #pragma unroll
    for (int o = 16; o > 0; o >>= 1) {
        lsum += __shfl_xor_sync(0xffffffffu, lsum, o);
        lcnt += __shfl_xor_sync(0xffffffffu, lcnt, o);
    }
    if (lane == 0) { rsum[w] = lsum; rcnt[w] = lcnt; }
    __syncthreads();
    if (t == 0) {
        float s = 0.0f; int c = 0;
        #pragma unroll
        for (int i = 0; i < NWARP; i++) { s += rsum[i]; c += rcnt[i]; }
        g_psum[bid] = s;
        g_pcnt[bid] = c;
        __threadfence();
        const u32 old = atomicAdd(&g_flag, 1u);
        s_last[0] = (old == NBLKS - 1) ? 1 : 0;
    }
    __syncthreads();

    // ---- Last block folds the 48 partials (deterministic order) ----
    if (s_last[0]) {
        float s2 = (t < NBLKS) ? g_psum[t] : 0.0f;
        int   c2 = (t < NBLKS) ? g_pcnt[t] : 0;
        #pragma unroll
        for (int o = 16; o > 0; o >>= 1) {
            s2 += __shfl_xor_sync(0xffffffffu, s2, o);
            c2 += __shfl_xor_sync(0xffffffffu, c2, o);
        }
        if (lane == 0 && w < 2) { rsum[w] = s2; rcnt[w] = c2; }
        __syncthreads();
        if (t == 0) {
            const float ts = rsum[0] + rsum[1];
            const int   tc = rcnt[0] + rcnt[1];
            out[0] = (tc > 0) ? (ts / (float)tc) : 0.0f;
            g_flag  = 0;   // reset for next graph replay
            g_ready = 0;
        }
    }
}

extern "C" void kernel_launch(void* const* d_in, const int* in_sizes, int n_in,
                              void* d_out, int out_size) {
    const float* e   = (const float*)d_in[0];
    const int*   lab = (const int*)d_in[1];
    cudaFuncSetAttribute(k_fused, cudaFuncAttributeMaxDynamicSharedMemorySize, SMEM_TOTAL);
    k_fused<<<NBLKS, NTHR, SMEM_TOTAL>>>(e, lab, (float*)d_out);
}

// round 17
// speedup vs baseline: 1.7568x; 1.0845x over previous
#include <cuda_runtime.h>
#include <cuda_bf16.h>
#include <cstdint>

#define Nn 384
#define Dm 256
#define MARGIN 0.2f
#define AB 8                 // anchors per group
#define NBLKS 96             // 48 groups x 2 j-halves
#define NTHR 384
#define NWARP 12
#define CH_ROWS 192          // rows per block (one half)
#define ROW_B 512            // bytes per bf16 row
#define HI_BYTES (CH_ROWS * ROW_B)          // 98304
#define OFF_LO   HI_BYTES
#define OFF_DROW (2 * HI_BYTES)             // 196608
#define OFF_SLAB (OFF_DROW + AB * CH_ROWS * 4)   // 202752
#define OFF_PD   (OFF_SLAB + Nn * 4)        // 204288
#define OFF_WCNT (OFF_PD + Nn * 4)          // 205824
#define OFF_RSUM (OFF_WCNT + NWARP * 4)
#define OFF_RCNT (OFF_RSUM + NWARP * 4)
#define OFF_SLAST (OFF_RCNT + NWARP * 4)
#define SMEM_TOTAL (OFF_SLAST + 16)

typedef unsigned u32;

__device__ __nv_bfloat16 g_ehi[Nn * Dm];
__device__ __nv_bfloat16 g_elo[Nn * Dm];
__device__ float g_D[Nn * Nn];
__device__ float g_psum[NBLKS];
__device__ int   g_pcnt[NBLKS];
__device__ u32   g_ready;   // zero-init; reset by last block each run
__device__ u32   g_flag;    // zero-init; reset by last block each run

static __device__ __forceinline__ u32 packbf(float a, float b) {
    __nv_bfloat162 h = __floats2bfloat162_rn(a, b);
    u32 r; memcpy(&r, &h, 4); return r;
}
static __device__ __forceinline__ u32 smem_u32(const void* p) {
    u32 a;
    asm("{ .reg .u64 t; cvta.to.shared.u64 t, %1; cvt.u32.u64 %0, t; }"
        : "=r"(a) : "l"(p));
    return a;
}
static __device__ __forceinline__ void cp16(u32 dst, const void* src) {
    asm volatile("cp.async.cg.shared.global [%0], [%1], 16;"
                 :: "r"(dst), "l"(src));
}
static __device__ __forceinline__ void ldm4(u32& r0, u32& r1, u32& r2, u32& r3, u32 addr) {
    asm volatile("ldmatrix.sync.aligned.m8n8.x4.shared.b16 {%0,%1,%2,%3}, [%4];"
                 : "=r"(r0), "=r"(r1), "=r"(r2), "=r"(r3) : "r"(addr));
}
static __device__ __forceinline__ void mma_bf16(
    float& c0, float& c1, float& c2, float& c3,
    u32 a0, u32 a1, u32 a2, u32 a3, u32 b0, u32 b1) {
    asm volatile(
        "mma.sync.aligned.m16n8k16.row.col.f32.bf16.bf16.f32 "
        "{%0,%1,%2,%3},{%4,%5,%6,%7},{%8,%9},{%0,%1,%2,%3};"
        : "+f"(c0), "+f"(c1), "+f"(c2), "+f"(c3)
        : "r"(a0), "r"(a1), "r"(a2), "r"(a3), "r"(b0), "r"(b1));
}

__global__ void __launch_bounds__(NTHR, 1)
k_fused(const float* __restrict__ e, const int* __restrict__ lab,
        float* __restrict__ out) {
    extern __shared__ __align__(1024) char sm[];
    float (*Drow)[CH_ROWS] = (float(*)[CH_ROWS])(sm + OFF_DROW);
    int*   slab = (int*)(sm + OFF_SLAB);
    float* pd   = (float*)(sm + OFF_PD);
    int*   wcnt = (int*)(sm + OFF_WCNT);
    float* rsum = (float*)(sm + OFF_RSUM);
    int*   rcnt = (int*)(sm + OFF_RCNT);
    int*   s_last = (int*)(sm + OFF_SLAST);
    const u32 sbase = smem_u32(sm);

    const int t = threadIdx.x, w = t >> 5, lane = t & 31;
    const int bid = blockIdx.x;
    const int grp = bid >> 1, h = bid & 1;
    const int a0g = grp * AB;
    const int jbase = h * CH_ROWS;
    const int gr  = lane >> 2;     // mma groupID (0..7)
    const int tig = lane & 3;      // mma thread-in-group (0..3)

    if (t < Nn) slab[t] = lab[t];

    // ---- Phase A: normalize rows bid*4..bid*4+3, store bf16 hi/lo splits ----
    if (w < 4) {
        const int row = bid * 4 + w;
        const float4* src = (const float4*)(e + row * Dm);
        float4 x0 = src[lane], x1 = src[lane + 32];
        float s = x0.x * x0.x;
        s = fmaf(x0.y, x0.y, s); s = fmaf(x0.z, x0.z, s); s = fmaf(x0.w, x0.w, s);
        s = fmaf(x1.x, x1.x, s); s = fmaf(x1.y, x1.y, s);
        s = fmaf(x1.z, x1.z, s); s = fmaf(x1.w, x1.w, s);
        #pragma unroll
        for (int o = 16; o > 0; o >>= 1) s += __shfl_xor_sync(0xffffffffu, s, o);
        const float inv = rsqrtf(fmaxf(s, 1e-24f));
        float nv[8] = { x0.x * inv, x0.y * inv, x0.z * inv, x0.w * inv,
                        x1.x * inv, x1.y * inv, x1.z * inv, x1.w * inv };
        float hi[8], lo[8];
        #pragma unroll
        for (int i = 0; i < 8; i++) {
            __nv_bfloat16 hb = __float2bfloat16(nv[i]);
            hi[i] = __bfloat162float(hb);
            lo[i] = nv[i] - hi[i];
        }
        u32* dh = (u32*)(g_ehi + row * Dm);
        u32* dl = (u32*)(g_elo + row * Dm);
        dh[lane * 2 + 0]      = packbf(hi[0], hi[1]);
        dh[lane * 2 + 1]      = packbf(hi[2], hi[3]);
        dh[64 + lane * 2 + 0] = packbf(hi[4], hi[5]);
        dh[64 + lane * 2 + 1] = packbf(hi[6], hi[7]);
        dl[lane * 2 + 0]      = packbf(lo[0], lo[1]);
        dl[lane * 2 + 1]      = packbf(lo[2], lo[3]);
        dl[64 + lane * 2 + 0] = packbf(lo[4], lo[5]);
        dl[64 + lane * 2 + 1] = packbf(lo[6], lo[7]);
    }
    __syncthreads();

    // ---- Grid barrier 1: all normalized rows visible ----
    if (t == 0) {
        __threadfence();
        atomicAdd(&g_ready, 1u);
        while (*(volatile u32*)&g_ready < (u32)NBLKS) { }
        __threadfence();
    }
    __syncthreads();

    // ---- Hoist B fragments (group's 8 anchors) into registers ----
    u32 bh[32], bl[32];
    {
        const u32* Bh32 = (const u32*)(g_ehi + (a0g + gr) * Dm);
        const u32* Bl32 = (const u32*)(g_elo + (a0g + gr) * Dm);
        #pragma unroll
        for (int kt = 0; kt < 16; kt++) {
            bh[2 * kt + 0] = Bh32[kt * 8 + tig];
            bh[2 * kt + 1] = Bh32[kt * 8 + tig + 4];
            bl[2 * kt + 0] = Bl32[kt * 8 + tig];
            bl[2 * kt + 1] = Bl32[kt * 8 + tig + 4];
        }
    }

    // ---- Phase B: stage this block's 192-row j-half, ldmatrix + mma ----
    #pragma unroll
    for (int i = 0; i < 16; i++) {
        const int u = t + i * NTHR;
        const int r = u >> 5, q = u & 31;
        const u32 off = (u32)(r * ROW_B) + (((u32)(q * 16)) ^ ((u32)(r & 7) << 4));
        cp16(sbase + off, (const char*)g_ehi + (jbase + r) * ROW_B + q * 16);
        cp16(sbase + OFF_LO + off, (const char*)g_elo + (jbase + r) * ROW_B + q * 16);
    }
    asm volatile("cp.async.commit_group;");
    asm volatile("cp.async.wait_group 0;");
    __syncthreads();

    {
        const int m_ = lane >> 3, rr = lane & 7;
        const u32 lm_row = (u32)(w * 16 + ((m_ & 1) << 3) + rr);   // 0..191
        const u32 lm_base = sbase + lm_row * ROW_B;
        const u32 lm_xm = (lm_row & 7) << 4;
        const u32 cb2 = (u32)(m_ >> 1) << 4;

        float hh0 = 0.f, hh1 = 0.f, hh2 = 0.f, hh3 = 0.f;
        float hl0 = 0.f, hl1 = 0.f, hl2 = 0.f, hl3 = 0.f;
        float lh0 = 0.f, lh1 = 0.f, lh2 = 0.f, lh3 = 0.f;
        #pragma unroll
        for (int kt = 0; kt < 16; kt++) {
            const u32 col = ((u32)(kt * 32) + cb2) ^ lm_xm;
            u32 ah0, ah1, ah2, ah3, al0, al1, al2, al3;
            ldm4(ah0, ah1, ah2, ah3, lm_base + col);
            ldm4(al0, al1, al2, al3, lm_base + OFF_LO + col);
            mma_bf16(hh0, hh1, hh2, hh3, ah0, ah1, ah2, ah3, bh[2*kt], bh[2*kt+1]);
            mma_bf16(hl0, hl1, hl2, hl3, ah0, ah1, ah2, ah3, bl[2*kt], bl[2*kt+1]);
            mma_bf16(lh0, lh1, lh2, lh3, al0, al1, al2, al3, bh[2*kt], bh[2*kt+1]);
        }
        const int j0 = w * 16;   // local j within half
        const float g0 = hh0 + hl0 + lh0;
        const float g1 = hh1 + hl1 + lh1;
        const float g2 = hh2 + hl2 + lh2;
        const float g3 = hh3 + hl3 + lh3;
        const int aA = 2 * tig, aBx = 2 * tig + 1;
        float d2, dv;
        d2 = fmaxf(2.0f - 2.0f * g0, 0.0f);
        dv = (d2 > 0.0f) ? sqrtf(d2) : 0.0f;
        Drow[aA][j0 + gr] = dv;      g_D[(a0g + aA) * Nn + jbase + j0 + gr] = dv;
        d2 = fmaxf(2.0f - 2.0f * g1, 0.0f);
        dv = (d2 > 0.0f) ? sqrtf(d2) : 0.0f;
        Drow[aBx][j0 + gr] = dv;     g_D[(a0g + aBx) * Nn + jbase + j0 + gr] = dv;
        d2 = fmaxf(2.0f - 2.0f * g2, 0.0f);
        dv = (d2 > 0.0f) ? sqrtf(d2) : 0.0f;
        Drow[aA][j0 + gr + 8] = dv;  g_D[(a0g + aA) * Nn + jbase + j0 + gr + 8] = dv;
        d2 = fmaxf(2.0f - 2.0f * g3, 0.0f);
        dv = (d2 > 0.0f) ? sqrtf(d2) : 0.0f;
        Drow[aBx][j0 + gr + 8] = dv; g_D[(a0g + aBx) * Nn + jbase + j0 + gr + 8] = dv;
    }
    __syncthreads();

    // ---- Grid barrier 2: full g_D visible ----
    if (t == 0) {
        __threadfence();
        atomicAdd(&g_ready, 1u);
        while (*(volatile u32*)&g_ready < (u32)(2 * NBLKS)) { }
        __threadfence();
    }
    __syncthreads();

    // ---- Phase C: positives from full g_D row; negatives from own half ----
    const int myl = slab[t];
    float lsum = 0.0f;
    int   lcnt = 0;
    #pragma unroll 1
    for (int aa = 0; aa < AB; aa++) {
        const int a  = a0g + aa;
        const int la = slab[a];
        const bool isp = (myl == la) && (t != a);
        const unsigned m = __ballot_sync(0xffffffffu, isp);
        if (lane == 0) wcnt[w] = __popc(m);
        __syncthreads();
        int off = 0, npos = 0;
        #pragma unroll
        for (int i = 0; i < NWARP; i++) {
            const int cc = wcnt[i];
            if (i < w) off += cc;
            npos += cc;
        }
        if (isp) pd[off + __popc(m & ((1u << lane) - 1u))] = g_D[a * Nn + t];
        __syncthreads();

        if (t < CH_ROWS && slab[jbase + t] != la) {
            const float dn = Drow[aa][t];
            for (int i = 0; i < npos; i++) {
                const float tm = dn - pd[i];
                // semihard & loss>0  <=>  0 < tm < MARGIN (tm==MARGIN adds 0)
                if (tm > 0.0f && tm < MARGIN) { lsum += (MARGIN - tm); lcnt++; }
            }
        }
        __syncthreads();
    }

    // ---- Block reduction (fixed order, deterministic) ----
    #pragma unroll
    for (int o = 16; o > 0; o >>= 1) {
        lsum += __shfl_xor_sync(0xffffffffu, lsum, o);
        lcnt += __shfl_xor_sync(0xffffffffu, lcnt, o);
    }
    if (lane == 0) { rsum[w] = lsum; rcnt[w] = lcnt; }
    __syncthreads();
    if (t == 0) {
        float s = 0.0f; int c = 0;
        #pragma unroll
        for (int i = 0; i < NWARP; i++) { s += rsum[i]; c += rcnt[i]; }
        g_psum[bid] = s;
        g_pcnt[bid] = c;
        __threadfence();
        const u32 old = atomicAdd(&g_flag, 1u);
        s_last[0] = (old == NBLKS - 1) ? 1 : 0;
    }
    __syncthreads();

    // ---- Last block folds the 96 partials (deterministic order) ----
    if (s_last[0]) {
        float s2 = (t < NBLKS) ? g_psum[t] : 0.0f;
        int   c2 = (t < NBLKS) ? g_pcnt[t] : 0;
        #pragma unroll
        for (int o = 16; o > 0; o >>= 1) {
            s2 += __shfl_xor_sync(0xffffffffu, s2, o);
            c2 += __shfl_xor_sync(0xffffffffu, c2, o);
        }
        if (lane == 0 && w < 3) { rsum[w] = s2; rcnt[w] = c2; }
        __syncthreads();
        if (t == 0) {
            const float ts = rsum[0] + rsum[1] + rsum[2];
            const int   tc = rcnt[0] + rcnt[1] + rcnt[2];
            out[0] = (tc > 0) ? (ts / (float)tc) : 0.0f;
            g_flag  = 0;   // reset for next graph replay
            g_ready = 0;
        }
    }
}

extern "C" void kernel_launch(void* const* d_in, const int* in_sizes, int n_in,
                              void* d_out, int out_size) {
    const float* e   = (const float*)d_in[0];
    const int*   lab = (const int*)d_in[1];
    cudaFuncSetAttribute(k_fused, cudaFuncAttributeMaxDynamicSharedMemorySize, SMEM_TOTAL);
    k_fused<<<NBLKS, NTHR, SMEM_TOTAL>>>(e, lab, (float*)d_out);
}